// round 2
// baseline (speedup 1.0000x reference)
#include <cuda_runtime.h>

// TensorialCP encoder: out[n, c] = Sx[c](x_n) * Sy[c](y_n) * Sz[c](z_n)
// where S is 1-D bilinear sampling of a [32, 512] table, align_corners=True.
//
// Strategy:
//  - All three tables (192 KB) live in shared memory, transposed to
//    [axis][r][c] with row stride 36 floats (16B-aligned float4 reads,
//    conflict-free row reads, 4-way conflicts only on one-time init writes).
//  - Warp processes 4 points: 8 lanes per point, each lane covers 4
//    components via float4 LDS. Output is a fully-coalesced 512B/warp store.
//  - 1 CTA/SM (216 KB smem), 1024 threads, grid-stride over points with a
//    one-iteration position prefetch.

#define NCOMP 32
#define RES   512
#define RSTRIDE 36                        // floats per row (144 B, 16B aligned)
#define AXSTRIDE (RES * RSTRIDE)          // floats per axis table
#define SMEM_FLOATS (3 * AXSTRIDE)
#define SMEM_BYTES (SMEM_FLOATS * 4)      // 221184 B = 216 KB

__device__ __forceinline__ float4 samp_axis(const float* __restrict__ axbase,
                                            float coord) {
    // map [-1,1] -> [0, 511]
    float ix = fmaf(coord, 255.5f, 255.5f);
    float fi = floorf(ix);
    fi = fminf(fmaxf(fi, 0.0f), 510.0f);   // safety clamp (no-op in-domain)
    float w  = ix - fi;
    int i0 = (int)fi;
    const float4* r0 = (const float4*)(axbase + i0 * RSTRIDE);
    const float4* r1 = (const float4*)(axbase + i0 * RSTRIDE + RSTRIDE);
    float4 g0 = *r0;
    float4 g1 = *r1;
    float4 o;
    o.x = fmaf(w, g1.x - g0.x, g0.x);
    o.y = fmaf(w, g1.y - g0.y, g0.y);
    o.z = fmaf(w, g1.z - g0.z, g0.z);
    o.w = fmaf(w, g1.w - g0.w, g0.w);
    return o;
}

__global__ __launch_bounds__(1024, 1)
void cp_encoder_kernel(const float* __restrict__ pos,
                       const float* __restrict__ vx,
                       const float* __restrict__ vy,
                       const float* __restrict__ vz,
                       float* __restrict__ out,
                       int N, int totalWarps) {
    extern __shared__ float tab[];

    // ---- load + transpose tables into smem: tab[a][r][c] ----
    // i = a*16384 + c*512 + r ; global read coalesced over r.
    int tid = threadIdx.x;
#pragma unroll
    for (int k = 0; k < 48; k++) {
        int i   = tid + (k << 10);        // blockDim fixed at 1024
        int a   = i >> 14;
        int rem = i & 16383;
        int c   = rem >> 9;
        int r   = rem & 511;
        const float* src = (a == 0) ? vx : ((a == 1) ? vy : vz);
        tab[a * AXSTRIDE + r * RSTRIDE + c] = src[(c << 9) + r];
    }
    __syncthreads();

    int lane = tid & 31;
    int sub  = lane >> 3;                 // which of the warp's 4 points
    int cl   = lane & 7;                  // component group: comps 4*cl..4*cl+3

    const float* bx = tab + 0 * AXSTRIDE + (cl << 2);
    const float* by = tab + 1 * AXSTRIDE + (cl << 2);
    const float* bz = tab + 2 * AXSTRIDE + (cl << 2);

    int warpGlobal = blockIdx.x * (blockDim.x >> 5) + (tid >> 5);
    int stride     = totalWarps * 4;      // points consumed per warp per iter
    int p          = warpGlobal * 4 + sub;

    // one-iteration position prefetch to hide HBM latency
    bool v = (p < N);
    float x = 0.f, y = 0.f, z = 0.f;
    if (v) {
        x = __ldg(&pos[3 * p + 0]);
        y = __ldg(&pos[3 * p + 1]);
        z = __ldg(&pos[3 * p + 2]);
    }

    while (v) {
        int  pn = p + stride;
        bool vn = (pn < N);
        float nx = 0.f, ny = 0.f, nz = 0.f;
        if (vn) {
            nx = __ldg(&pos[3 * pn + 0]);
            ny = __ldg(&pos[3 * pn + 1]);
            nz = __ldg(&pos[3 * pn + 2]);
        }

        float4 fx = samp_axis(bx, x);
        float4 fy = samp_axis(by, y);
        float4 fz = samp_axis(bz, z);

        float4 o;
        o.x = fx.x * fy.x * fz.x;
        o.y = fx.y * fy.y * fz.y;
        o.z = fx.z * fy.z * fz.z;
        o.w = fx.w * fy.w * fz.w;

        *(float4*)(out + ((size_t)p << 5) + (cl << 2)) = o;

        p = pn; v = vn; x = nx; y = ny; z = nz;
    }
}

extern "C" void kernel_launch(void* const* d_in, const int* in_sizes, int n_in,
                              void* d_out, int out_size) {
    const float* pos = (const float*)d_in[0];
    const float* vx  = (const float*)d_in[1];
    const float* vy  = (const float*)d_in[2];
    const float* vz  = (const float*)d_in[3];
    float* out = (float*)d_out;

    int N = in_sizes[0] / 3;

    int dev = 0;
    cudaGetDevice(&dev);
    int sms = 148;
    cudaDeviceGetAttribute(&sms, cudaDevAttrMultiProcessorCount, dev);

    cudaFuncSetAttribute(cp_encoder_kernel,
                         cudaFuncAttributeMaxDynamicSharedMemorySize,
                         SMEM_BYTES);

    int totalWarps = sms * (1024 / 32);
    cp_encoder_kernel<<<sms, 1024, SMEM_BYTES>>>(pos, vx, vy, vz, out, N,
                                                 totalWarps);
}

// round 8
// speedup vs baseline: 1.4733x; 1.4733x over previous
#include <cuda_runtime.h>
#include <cuda_fp16.h>

// TensorialCP encoder: out[n, c] = Sx[c](x_n) * Sy[c](y_n) * Sz[c](z_n)
// 1-D bilinear sampling of three [32, 512] tables, align_corners=True.
//
// Key trick: pack (g[r], g[r+1]) per component as half2 -> one 128B
// conflict-free LDS.128 row read per axis per point delivers BOTH lerp
// endpoints. Halves smem-crossbar bytes vs fp32 and halves LDS count.
// All interpolation / product math stays fp32 (only storage is fp16).

#define NCOMP 32
#define RES   512
#define PAIRS_PER_AXIS (RES * NCOMP)          // 16384 half2
#define PAIRS_TOTAL    (3 * PAIRS_PER_AXIS)   // 49152 half2 = 192 KB
#define SMEM_BYTES     (PAIRS_TOTAL * 4)      // 196608 B

// Packed pair table scratch (built once per launch by prep kernel).
__device__ __half2 g_pairs[PAIRS_TOTAL];

// ---------------- prep: build half2 pair table -------------------------
// layout: g_pairs[a*16384 + r*32 + c] = (g_a[c][r], g_a[c][r+1])
// i consecutive -> c fastest -> coalesced writes. Reads are strided but
// tiny (~12 MB of sector traffic total, ~2us).
__global__ void cp_prep_kernel(const float* __restrict__ vx,
                               const float* __restrict__ vy,
                               const float* __restrict__ vz) {
    int i = blockIdx.x * blockDim.x + threadIdx.x;
    if (i >= PAIRS_TOTAL) return;
    int a   = i >> 14;
    int rem = i & 16383;
    int r   = rem >> 5;
    int c   = rem & 31;
    const float* src = (a == 0) ? vx : ((a == 1) ? vy : vz);
    float lo = src[(c << 9) + r];
    float hi = (r < RES - 1) ? src[(c << 9) + r + 1] : 0.0f;
    g_pairs[i] = __floats2half2_rn(lo, hi);
}

// ---------------- main kernel ------------------------------------------
// Warp = 4 points, 8 lanes/point, lane covers 4 components.
// Per point per axis: ONE LDS.128 (4 half2 pairs), then fp32 lerp.
// Output: warp stores 512B contiguous (4 pts x 128B), streaming.

__device__ __forceinline__ void samp_axis_pair(const __half2* __restrict__ rowbase,
                                               float coord, float4& f) {
    float ix = fmaf(coord, 255.5f, 255.5f);     // [-1,1] -> [0,511]
    float fi = floorf(ix);
    fi = fminf(fmaxf(fi, 0.0f), 510.0f);
    float w  = ix - fi;
    int i0 = (int)fi;
    // row = 32 half2 = 128B; lane's 4 pairs are 16B aligned
    uint4 u = *(const uint4*)(rowbase + (i0 << 5));
    const __half2* h = (const __half2*)&u;
    float2 p0 = __half22float2(h[0]);
    float2 p1 = __half22float2(h[1]);
    float2 p2 = __half22float2(h[2]);
    float2 p3 = __half22float2(h[3]);
    f.x = fmaf(w, p0.y - p0.x, p0.x);
    f.y = fmaf(w, p1.y - p1.x, p1.x);
    f.z = fmaf(w, p2.y - p2.x, p2.x);
    f.w = fmaf(w, p3.y - p3.x, p3.x);
}

__global__ __launch_bounds__(1024, 1)
void cp_encoder_kernel(const float* __restrict__ pos,
                       float* __restrict__ out,
                       int N, int totalWarps) {
    extern __shared__ __half2 tab[];

    int tid = threadIdx.x;

    // Linear, fully-coalesced, conflict-free 192KB smem fill (L2-resident).
    {
        const float4* gp = (const float4*)g_pairs;
        float4*       sp = (float4*)tab;
#pragma unroll
        for (int k = 0; k < 12; k++) {
            sp[tid + (k << 10)] = gp[tid + (k << 10)];
        }
    }
    __syncthreads();

    int lane = tid & 31;
    int sub  = lane >> 3;                 // which of the warp's 4 points
    int cl   = lane & 7;                  // component group (4 comps)

    const __half2* bx = tab + 0 * PAIRS_PER_AXIS + (cl << 2);
    const __half2* by = tab + 1 * PAIRS_PER_AXIS + (cl << 2);
    const __half2* bz = tab + 2 * PAIRS_PER_AXIS + (cl << 2);

    int warpGlobal = blockIdx.x * (blockDim.x >> 5) + (tid >> 5);
    int stride     = totalWarps * 4;
    int p          = warpGlobal * 4 + sub;

    // one-iteration position prefetch
    bool v = (p < N);
    float x = 0.f, y = 0.f, z = 0.f;
    if (v) {
        x = __ldg(&pos[3 * p + 0]);
        y = __ldg(&pos[3 * p + 1]);
        z = __ldg(&pos[3 * p + 2]);
    }

    while (v) {
        int  pn = p + stride;
        bool vn = (pn < N);
        float nx = 0.f, ny = 0.f, nz = 0.f;
        if (vn) {
            nx = __ldg(&pos[3 * pn + 0]);
            ny = __ldg(&pos[3 * pn + 1]);
            nz = __ldg(&pos[3 * pn + 2]);
        }

        float4 fx, fy, fz;
        samp_axis_pair(bx, x, fx);
        samp_axis_pair(by, y, fy);
        samp_axis_pair(bz, z, fz);

        float4 o;
        o.x = fx.x * fy.x * fz.x;
        o.y = fx.y * fy.y * fz.y;
        o.z = fx.z * fy.z * fz.z;
        o.w = fx.w * fy.w * fz.w;

        // streaming store: 256MB write-once, keep it out of L2's way
        __stcs((float4*)(out + ((size_t)p << 5) + (cl << 2)), o);

        p = pn; v = vn; x = nx; y = ny; z = nz;
    }
}

extern "C" void kernel_launch(void* const* d_in, const int* in_sizes, int n_in,
                              void* d_out, int out_size) {
    const float* pos = (const float*)d_in[0];
    const float* vx  = (const float*)d_in[1];
    const float* vy  = (const float*)d_in[2];
    const float* vz  = (const float*)d_in[3];
    float* out = (float*)d_out;

    int N = in_sizes[0] / 3;

    int sms = 148;
    cudaDeviceGetAttribute(&sms, cudaDevAttrMultiProcessorCount, 0);

    cudaFuncSetAttribute(cp_encoder_kernel,
                         cudaFuncAttributeMaxDynamicSharedMemorySize,
                         SMEM_BYTES);

    cp_prep_kernel<<<(PAIRS_TOTAL + 255) / 256, 256>>>(vx, vy, vz);

    int totalWarps = sms * (1024 / 32);
    cp_encoder_kernel<<<sms, 1024, SMEM_BYTES>>>(pos, out, N, totalWarps);
}

// round 10
// speedup vs baseline: 1.8141x; 1.2313x over previous
#include <cuda_runtime.h>
#include <cuda_fp16.h>

// TensorialCP encoder: out[n, c] = Sx[c](x_n) * Sy[c](y_n) * Sz[c](z_n)
// 1-D bilinear sampling of three [32, 512] tables, align_corners=True.
//
// R9: fp16 HFMA2 lerp. Table packed per row (128B) as 8 groups of
// [lo0 lo1 lo2 lo3 | d0 d1 d2 d3] halves (d = g[r+1]-g[r]), so each lane's
// 16B LDS.128 delivers 4 components' lerp endpoints in HFMA2-ready form:
//   r01 = hfma2(w2, d01, lo01); r23 = hfma2(w2, d23, lo23)
// Products + output remain fp32. One conflict-free LDS.128 per axis/point.

#define NCOMP 32
#define RES   512
#define HALVES_PER_ROW  64                    // 32 lo + 32 d, interleaved by 4
#define HALVES_PER_AXIS (RES * HALVES_PER_ROW)    // 32768
#define HALVES_TOTAL    (3 * HALVES_PER_AXIS)     // 98304 halves = 192 KB
#define SMEM_BYTES      (HALVES_TOTAL * 2)        // 196608 B

__device__ __half g_tab[HALVES_TOTAL];

// ---------------- prep: build (lo, d) half table -----------------------
// half index: a*32768 + r*64 + (c>>2)*8 + (c&3)  -> lo ; +4 -> d
__global__ void cp_prep_kernel(const float* __restrict__ vx,
                               const float* __restrict__ vy,
                               const float* __restrict__ vz) {
    int i = blockIdx.x * blockDim.x + threadIdx.x;
    if (i >= 3 * RES * NCOMP) return;
    int a   = i >> 14;
    int rem = i & 16383;
    int r   = rem >> 5;
    int c   = rem & 31;
    const float* src = (a == 0) ? vx : ((a == 1) ? vy : vz);
    float lo = src[(c << 9) + r];
    float hi = (r < RES - 1) ? src[(c << 9) + r + 1] : lo;  // d=0 at r=511
    int base = a * HALVES_PER_AXIS + (r << 6) + ((c >> 2) << 3) + (c & 3);
    g_tab[base]     = __float2half_rn(lo);
    g_tab[base + 4] = __float2half_rn(hi - lo);
}

// ---------------- main kernel ------------------------------------------
// Warp = 4 points, 8 lanes/point, lane covers 4 components.

__device__ __forceinline__ void samp_axis(const __half* __restrict__ axbase,
                                          float coord, float4& f) {
    float ix = fmaf(coord, 255.5f, 255.5f);     // [-1,1] -> [0,511]
    float fi = floorf(ix);
    float w  = ix - fi;
    int i0 = (int)fi;                           // in [0,511] by construction
    uint4 u = *(const uint4*)(axbase + (i0 << 6));
    const __half2* h = (const __half2*)&u;      // h[0]=lo01 h[1]=lo23 h[2]=d01 h[3]=d23
    __half2 w2 = __float2half2_rn(w);
    __half2 r01 = __hfma2(w2, h[2], h[0]);
    __half2 r23 = __hfma2(w2, h[3], h[1]);
    float2 f01 = __half22float2(r01);
    float2 f23 = __half22float2(r23);
    f.x = f01.x; f.y = f01.y; f.z = f23.x; f.w = f23.y;
}

__global__ __launch_bounds__(1024, 1)
void cp_encoder_kernel(const float* __restrict__ pos,
                       float* __restrict__ out,
                       int N, int totalWarps) {
    extern __shared__ __half tab[];

    int tid = threadIdx.x;

    // Linear, coalesced, conflict-free 192KB smem fill (L2-resident).
    {
        const float4* gp = (const float4*)g_tab;
        float4*       sp = (float4*)tab;
#pragma unroll
        for (int k = 0; k < 12; k++) {
            sp[tid + (k << 10)] = gp[tid + (k << 10)];
        }
    }
    __syncthreads();

    int lane = tid & 31;
    int sub  = lane >> 3;                 // which of the warp's 4 points
    int cl   = lane & 7;                  // component group (4 comps)

    const __half* bx = tab + 0 * HALVES_PER_AXIS + (cl << 3);
    const __half* by = tab + 1 * HALVES_PER_AXIS + (cl << 3);
    const __half* bz = tab + 2 * HALVES_PER_AXIS + (cl << 3);

    int warpGlobal = blockIdx.x * (blockDim.x >> 5) + (tid >> 5);
    int stride     = totalWarps * 4;
    int p          = warpGlobal * 4 + sub;

    // one-iteration position prefetch
    bool v = (p < N);
    float x = 0.f, y = 0.f, z = 0.f;
    if (v) {
        x = __ldg(&pos[3 * p + 0]);
        y = __ldg(&pos[3 * p + 1]);
        z = __ldg(&pos[3 * p + 2]);
    }

    while (v) {
        int  pn = p + stride;
        bool vn = (pn < N);
        float nx = 0.f, ny = 0.f, nz = 0.f;
        if (vn) {
            nx = __ldg(&pos[3 * pn + 0]);
            ny = __ldg(&pos[3 * pn + 1]);
            nz = __ldg(&pos[3 * pn + 2]);
        }

        float4 fx, fy, fz;
        samp_axis(bx, x, fx);
        samp_axis(by, y, fy);
        samp_axis(bz, z, fz);

        float4 o;
        o.x = fx.x * fy.x * fz.x;
        o.y = fx.y * fy.y * fz.y;
        o.z = fx.z * fy.z * fz.z;
        o.w = fx.w * fy.w * fz.w;

        // streaming store: 256MB write-once, keep it out of L2's way
        __stcs((float4*)(out + ((size_t)p << 5) + (cl << 2)), o);

        p = pn; v = vn; x = nx; y = ny; z = nz;
    }
}

extern "C" void kernel_launch(void* const* d_in, const int* in_sizes, int n_in,
                              void* d_out, int out_size) {
    const float* pos = (const float*)d_in[0];
    const float* vx  = (const float*)d_in[1];
    const float* vy  = (const float*)d_in[2];
    const float* vz  = (const float*)d_in[3];
    float* out = (float*)d_out;

    int N = in_sizes[0] / 3;

    int sms = 148;
    cudaDeviceGetAttribute(&sms, cudaDevAttrMultiProcessorCount, 0);

    cudaFuncSetAttribute(cp_encoder_kernel,
                         cudaFuncAttributeMaxDynamicSharedMemorySize,
                         SMEM_BYTES);

    cp_prep_kernel<<<(3 * RES * NCOMP + 255) / 256, 256>>>(vx, vy, vz);

    int totalWarps = sms * (1024 / 32);
    cp_encoder_kernel<<<sms, 1024, SMEM_BYTES>>>(pos, out, N, totalWarps);
}